// round 5
// baseline (speedup 1.0000x reference)
#include <cuda_runtime.h>
#include <cuda_fp16.h>
#include <cstdint>

#define BQ   2
#define SEQ  2048
#define DIMC 1024
#define NH   16
#define DH   64
#define QKVC 3072
#define NROWS (BQ*SEQ)

// ---- device scratch ----
__device__ __half g_xnh[(size_t)NROWS * DIMC];            // 8 MB    LN out (fp16)
__device__ __half g_qkvh[(size_t)NROWS * QKVC];           // 25 MB   [q*0.125 | k | v] fp16
__device__ float  g_dots[(size_t)BQ * NH * SEQ * SEQ];    // 512 MB  raw mixed... raw dots f32
__device__ __half g_prh[(size_t)BQ * NH * SEQ * SEQ];     // 256 MB  post-mix probs fp16
__device__ __half g_aoh[(size_t)BQ * NH * SEQ * DH];      // 8 MB    [b,g,i,d] fp16
__device__ __half g_wqth[(size_t)DIMC * DIMC];            // Wq^T  [n][k] fp16
__device__ __half g_wkvth[(size_t)2 * DIMC * DIMC];       // Wkv^T [n][k] fp16
__device__ __half g_woutth[(size_t)DIMC * DIMC];          // Wout^T[n][k] fp16
__device__ __half g_vth[(size_t)BQ * NH * DH * SEQ];      // V^T per (b,g): [d][j] fp16

#define MMA_F16(c, a, b) \
    asm volatile("mma.sync.aligned.m16n8k16.row.col.f32.f16.f16.f32 " \
        "{%0,%1,%2,%3}, {%4,%5,%6,%7}, {%8,%9}, {%0,%1,%2,%3};" \
        : "+f"((c)[0]), "+f"((c)[1]), "+f"((c)[2]), "+f"((c)[3]) \
        : "r"((a)[0]), "r"((a)[1]), "r"((a)[2]), "r"((a)[3]), \
          "r"((b)[0]), "r"((b)[1]))

// swizzled 4B load from a [rows][64-half] tile (128B rows, 16B chunk xor swizzle)
#define LDH(s, m, k) (*(const uint32_t*)((s) + (m)*128 + \
    ((((k) >> 3) ^ ((m) & 7)) << 4) + (((k) & 7) << 1)))

// ============================================================ fp16 GEMM engine
// C[128 x BN] = A[128 x 64*KB] @ Bt[BN x 64*KB]^T
// A tile addr: A + row*AR + kb*AK (halves). B: Bt + n*BR + kb*64.
template<int BN, int MT, bool OUTH>
__device__ __forceinline__ void gemm16(
    const __half* __restrict__ A, size_t AR, size_t AK,
    const __half* __restrict__ Bt, size_t BR,
    int KB, float cscale,
    void* __restrict__ Cv, int ldc, const float* __restrict__ bias)
{
    extern __shared__ char smx[];
    constexpr int ABY = 128 * 128;           // A tile bytes
    constexpr int BBY = BN * 128;
    constexpr int STG = ABY + BBY;
    constexpr int NT  = 4;
    constexpr int CPB = BN / 32;             // B uint4 chunks per thread

    int t = threadIdx.x, lane = t & 31, w = t >> 5;
    int wm = (BN == 128) ? (w & 1) * 64 : (w & 3) * 32;
    int wn = (BN == 128) ? (w >> 1) * 32 : (w >> 2) * 32;
    int lm = lane >> 2;

    int arow = t >> 1, ac0 = (t & 1) * 4;
    int brow = (BN == 128) ? (t >> 1) : (t >> 2);
    int bc0  = (BN == 128) ? (t & 1) * 4 : (t & 3);

    const __half* Abase = A + (size_t)arow * AR;
    const __half* Bbase = Bt + (size_t)brow * BR;

    uint4 aR[4], bR[CPB];
    float acc[MT][NT][4];
    #pragma unroll
    for (int mt = 0; mt < MT; mt++)
        #pragma unroll
        for (int nt = 0; nt < NT; nt++)
            #pragma unroll
            for (int i = 0; i < 4; i++) acc[mt][nt][i] = 0.f;

    // prologue: kb = 0
    {
        const uint4* ap = (const uint4*)Abase;
        #pragma unroll
        for (int c = 0; c < 4; c++) aR[c] = ap[ac0 + c];
        const uint4* bp = (const uint4*)Bbase;
        #pragma unroll
        for (int i = 0; i < CPB; i++)
            bR[i] = bp[(BN == 128) ? (bc0 + i) : (bc0 + i * 4)];
        char* sA = smx;
        char* sB = smx + ABY;
        #pragma unroll
        for (int c = 0; c < 4; c++)
            *(uint4*)(sA + arow * 128 + (((ac0 + c) ^ (arow & 7)) << 4)) = aR[c];
        #pragma unroll
        for (int i = 0; i < CPB; i++) {
            int c = (BN == 128) ? (bc0 + i) : (bc0 + i * 4);
            *(uint4*)(sB + brow * 128 + ((c ^ (brow & 7)) << 4)) = bR[i];
        }
    }
    __syncthreads();

    int stage = 0;
    for (int kb = 0; kb < KB; kb++) {
        bool more = (kb + 1 < KB);
        if (more) {
            const uint4* ap = (const uint4*)(Abase + (size_t)(kb + 1) * AK);
            #pragma unroll
            for (int c = 0; c < 4; c++) aR[c] = ap[ac0 + c];
            const uint4* bp = (const uint4*)(Bbase + (size_t)(kb + 1) * 64);
            #pragma unroll
            for (int i = 0; i < CPB; i++)
                bR[i] = bp[(BN == 128) ? (bc0 + i) : (bc0 + i * 4)];
        }
        const char* sA = smx + stage * STG;
        const char* sB = sA + ABY;
        #pragma unroll
        for (int ks = 0; ks < 4; ks++) {
            int kk = ks * 16 + (lane & 3) * 2;
            uint32_t af[MT][4], bf[NT][2];
            #pragma unroll
            for (int mt = 0; mt < MT; mt++) {
                int r = wm + mt * 16 + lm;
                af[mt][0] = LDH(sA, r,     kk);
                af[mt][1] = LDH(sA, r + 8, kk);
                af[mt][2] = LDH(sA, r,     kk + 8);
                af[mt][3] = LDH(sA, r + 8, kk + 8);
            }
            #pragma unroll
            for (int nt = 0; nt < NT; nt++) {
                int n = wn + nt * 8 + lm;
                bf[nt][0] = LDH(sB, n, kk);
                bf[nt][1] = LDH(sB, n, kk + 8);
            }
            #pragma unroll
            for (int mt = 0; mt < MT; mt++)
                #pragma unroll
                for (int nt = 0; nt < NT; nt++)
                    MMA_F16(acc[mt][nt], af[mt], bf[nt]);
        }
        if (more) {
            char* dA = smx + (stage ^ 1) * STG;
            char* dB = dA + ABY;
            #pragma unroll
            for (int c = 0; c < 4; c++)
                *(uint4*)(dA + arow * 128 + (((ac0 + c) ^ (arow & 7)) << 4)) = aR[c];
            #pragma unroll
            for (int i = 0; i < CPB; i++) {
                int c = (BN == 128) ? (bc0 + i) : (bc0 + i * 4);
                *(uint4*)(dB + brow * 128 + ((c ^ (brow & 7)) << 4)) = bR[i];
            }
            __syncthreads();
            stage ^= 1;
        }
    }

    // epilogue
    #pragma unroll
    for (int mt = 0; mt < MT; mt++) {
        int r0 = wm + mt * 16 + (lane >> 2);
        #pragma unroll
        for (int nt = 0; nt < NT; nt++) {
            int c0 = wn + nt * 8 + 2 * (lane & 3);
            float v0 = acc[mt][nt][0] * cscale, v1 = acc[mt][nt][1] * cscale;
            float v2 = acc[mt][nt][2] * cscale, v3 = acc[mt][nt][3] * cscale;
            if (OUTH) {
                __half* C = (__half*)Cv;
                *(__half2*)&C[(size_t)r0 * ldc + c0]       = __floats2half2_rn(v0, v1);
                *(__half2*)&C[(size_t)(r0 + 8) * ldc + c0] = __floats2half2_rn(v2, v3);
            } else {
                float* C = (float*)Cv;
                if (bias) {
                    float b0 = bias[c0], b1 = bias[c0 + 1];
                    v0 += b0; v1 += b1; v2 += b0; v3 += b1;
                }
                *(float2*)&C[(size_t)r0 * ldc + c0]       = make_float2(v0, v1);
                *(float2*)&C[(size_t)(r0 + 8) * ldc + c0] = make_float2(v2, v3);
            }
        }
    }
}

// ============================================================ LayerNorm -> fp16
__global__ void ln_kernel(const float* __restrict__ x,
                          const float* __restrict__ gamma,
                          const float* __restrict__ beta) {
    int row = blockIdx.x;
    int t = threadIdx.x;
    const float4* xr = (const float4*)(x + (size_t)row * DIMC);
    float4 v = xr[t];
    float s = v.x + v.y + v.z + v.w;
    float q = v.x*v.x + v.y*v.y + v.z*v.z + v.w*v.w;
    __shared__ float s_sum[8], s_sq[8];
    #pragma unroll
    for (int o = 16; o > 0; o >>= 1) {
        s += __shfl_xor_sync(0xffffffffu, s, o);
        q += __shfl_xor_sync(0xffffffffu, q, o);
    }
    if ((t & 31) == 0) { s_sum[t >> 5] = s; s_sq[t >> 5] = q; }
    __syncthreads();
    if (t < 32) {
        float a = (t < 8) ? s_sum[t] : 0.f;
        float c = (t < 8) ? s_sq[t] : 0.f;
        #pragma unroll
        for (int o = 4; o > 0; o >>= 1) {
            a += __shfl_xor_sync(0xffffffffu, a, o);
            c += __shfl_xor_sync(0xffffffffu, c, o);
        }
        if (t == 0) { s_sum[0] = a; s_sq[0] = c; }
    }
    __syncthreads();
    float mean = s_sum[0] * (1.f / DIMC);
    float var  = s_sq[0] * (1.f / DIMC) - mean * mean;
    float rs = rsqrtf(var + 1e-5f);
    float4 gg = ((const float4*)gamma)[t];
    float4 bb = ((const float4*)beta)[t];
    __half2 h0 = __floats2half2_rn((v.x - mean) * rs * gg.x + bb.x,
                                   (v.y - mean) * rs * gg.y + bb.y);
    __half2 h1 = __floats2half2_rn((v.z - mean) * rs * gg.z + bb.z,
                                   (v.w - mean) * rs * gg.w + bb.w);
    __half2* dst = (__half2*)(g_xnh + (size_t)row * DIMC);
    dst[2 * t]     = h0;
    dst[2 * t + 1] = h1;
}

// ============================================================ weight transpose f32 -> fp16 [n][k]
__global__ void wt_kernel(const float* __restrict__ src, __half* __restrict__ dst,
                          int R, int C) {
    __shared__ float tile[32][33];
    int tx = threadIdx.x, ty = threadIdx.y;
    int c0 = blockIdx.x * 32, r0 = blockIdx.y * 32;
    #pragma unroll
    for (int i = 0; i < 32; i += 8)
        tile[ty + i][tx] = src[(size_t)(r0 + ty + i) * C + c0 + tx];
    __syncthreads();
    #pragma unroll
    for (int i = 0; i < 32; i += 8)
        dst[(size_t)(c0 + ty + i) * R + r0 + tx] = __float2half(tile[tx][ty + i]);
}

// V slice of g_qkvh -> g_vth[z][d][j]
__global__ void vt_kernel() {
    __shared__ __half tile[32][40];
    int tx = threadIdx.x, ty = threadIdx.y;
    int z = blockIdx.z, b = z >> 4, g = z & 15;
    int d0 = blockIdx.x * 32, i0 = blockIdx.y * 32;
    const __half* src = g_qkvh + (size_t)b * SEQ * QKVC + 2048 + g * 64;
    #pragma unroll
    for (int i = 0; i < 32; i += 8)
        tile[ty + i][tx] = src[(size_t)(i0 + ty + i) * QKVC + d0 + tx];
    __syncthreads();
    __half* dst = g_vth + (size_t)z * DH * SEQ;
    #pragma unroll
    for (int i = 0; i < 32; i += 8)
        dst[(size_t)(d0 + ty + i) * SEQ + i0 + tx] = tile[tx][ty + i];
}

// ============================================================ GEMM wrappers
__global__ __launch_bounds__(256) void proj_k() {
    int m0 = blockIdx.y * 128, cb = blockIdx.x * 128;
    const __half* Bt = (cb < 1024) ? (g_wqth + (size_t)cb * DIMC)
                                   : (g_wkvth + (size_t)(cb - 1024) * DIMC);
    gemm16<128, 4, true>(g_xnh + (size_t)m0 * DIMC, DIMC, 64,
                         Bt, DIMC, DIMC / 64,
                         (cb < 1024) ? 0.125f : 1.0f,
                         g_qkvh + (size_t)m0 * QKVC + cb, QKVC, nullptr);
}

__global__ __launch_bounds__(256) void qk_k() {
    int z = blockIdx.z, b = z >> 4, h = z & 15;
    int m0 = blockIdx.y * 128, n0 = blockIdx.x * 128;
    const __half* base = g_qkvh + (size_t)b * SEQ * QKVC;
    gemm16<128, 4, false>(base + (size_t)m0 * QKVC + h * DH, QKVC, 64,
                          base + (size_t)n0 * QKVC + 1024 + h * DH, QKVC, 1,
                          1.0f,
                          g_dots + ((size_t)z * SEQ + m0) * SEQ + n0, SEQ, nullptr);
}

__global__ __launch_bounds__(256) void av_k() {
    int z = blockIdx.y, m0 = blockIdx.x * 128;
    gemm16<64, 2, true>(g_prh + (size_t)z * SEQ * SEQ + (size_t)m0 * SEQ, SEQ, 64,
                        g_vth + (size_t)z * DH * SEQ, SEQ, SEQ / 64,
                        1.0f,
                        g_aoh + ((size_t)z * SEQ + m0) * DH, DH, nullptr);
}

__global__ __launch_bounds__(256) void out_k(const float* __restrict__ bout,
                                             float* __restrict__ out) {
    int m0 = blockIdx.y * 128, n0 = blockIdx.x * 128;
    int b = m0 >> 11, i0 = m0 & (SEQ - 1);
    gemm16<128, 4, false>(g_aoh + ((size_t)(b * NH) * SEQ + i0) * DH, DH, (size_t)SEQ * DH,
                          g_woutth + (size_t)n0 * DIMC, DIMC, DIMC / 64,
                          1.0f,
                          out + (size_t)m0 * DIMC + n0, DIMC, bout + n0);
}

// ============================================================ pre-mix -> softmax -> post-mix
// reads g_dots (f32), writes g_prh (fp16)
__global__ __launch_bounds__(256)
void mixsoftmax_kernel(const float* __restrict__ mix_pre, const float* __restrict__ mix_post) {
    extern __shared__ float srow[];          // [NH][SEQ]
    __shared__ float mp[256], mq[256];
    __shared__ float red[NH][8];
    __shared__ float mg[NH], linv[NH];
    int t = threadIdx.x;
    int b = blockIdx.x >> 11;
    int i = blockIdx.x & (SEQ - 1);
    mp[t] = mix_pre[t];
    mq[t] = mix_post[t];
    size_t base = ((size_t)(b * NH) * SEQ + i) * SEQ;
    for (int h = 0; h < NH; h++) {
        const float4* src = (const float4*)(g_dots + base + (size_t)h * SEQ * SEQ);
        float4* dst = (float4*)(srow + h * SEQ);
        for (int j = t; j < SEQ/4; j += 256) dst[j] = src[j];
    }
    __syncthreads();
    float tmax[NH];
    #pragma unroll
    for (int g = 0; g < NH; g++) tmax[g] = -3.4e38f;
    for (int j = t; j < SEQ; j += 256) {
        float sh[NH];
        #pragma unroll
        for (int h = 0; h < NH; h++) sh[h] = srow[h*SEQ + j];
        #pragma unroll
        for (int g = 0; g < NH; g++) {
            float v = 0.f;
            #pragma unroll
            for (int h = 0; h < NH; h++) v = fmaf(mp[h*NH + g], sh[h], v);
            srow[g*SEQ + j] = v;
            tmax[g] = fmaxf(tmax[g], v);
        }
    }
    int w = t >> 5, l = t & 31;
    #pragma unroll
    for (int g = 0; g < NH; g++) {
        float v = tmax[g];
        #pragma unroll
        for (int o = 16; o > 0; o >>= 1) v = fmaxf(v, __shfl_xor_sync(0xffffffffu, v, o));
        if (l == 0) red[g][w] = v;
    }
    __syncthreads();
    if (t < NH) {
        float v = red[t][0];
        #pragma unroll
        for (int w2 = 1; w2 < 8; w2++) v = fmaxf(v, red[t][w2]);
        mg[t] = v;
    }
    __syncthreads();
    float tsum[NH];
    #pragma unroll
    for (int g = 0; g < NH; g++) tsum[g] = 0.f;
    for (int j = t; j < SEQ; j += 256) {
        #pragma unroll
        for (int g = 0; g < NH; g++) {
            float e = __expf(srow[g*SEQ + j] - mg[g]);
            srow[g*SEQ + j] = e;
            tsum[g] += e;
        }
    }
    __syncthreads();
    #pragma unroll
    for (int g = 0; g < NH; g++) {
        float v = tsum[g];
        #pragma unroll
        for (int o = 16; o > 0; o >>= 1) v += __shfl_xor_sync(0xffffffffu, v, o);
        if (l == 0) red[g][w] = v;
    }
    __syncthreads();
    if (t < NH) {
        float v = 0.f;
        #pragma unroll
        for (int w2 = 0; w2 < 8; w2++) v += red[t][w2];
        linv[t] = 1.f / v;
    }
    __syncthreads();
    // post-mix on normalized probs, fp16 half2 stores
    for (int j = 2 * t; j < SEQ; j += 512) {
        float p0[NH], p1[NH];
        #pragma unroll
        for (int h = 0; h < NH; h++) {
            p0[h] = srow[h*SEQ + j]     * linv[h];
            p1[h] = srow[h*SEQ + j + 1] * linv[h];
        }
        #pragma unroll
        for (int g = 0; g < NH; g++) {
            float v0 = 0.f, v1 = 0.f;
            #pragma unroll
            for (int h = 0; h < NH; h++) {
                v0 = fmaf(mq[h*NH + g], p0[h], v0);
                v1 = fmaf(mq[h*NH + g], p1[h], v1);
            }
            *(__half2*)&g_prh[base + (size_t)g*SEQ*SEQ + j] = __floats2half2_rn(v0, v1);
        }
    }
}

// ============================================================ launch
extern "C" void kernel_launch(void* const* d_in, const int* in_sizes, int n_in,
                              void* d_out, int out_size) {
    const float* x       = (const float*)d_in[0];
    const float* ln_g    = (const float*)d_in[1];
    const float* ln_b    = (const float*)d_in[2];
    const float* Wq      = (const float*)d_in[3];
    const float* Wkv     = (const float*)d_in[4];
    const float* mixpre  = (const float*)d_in[5];
    const float* mixpost = (const float*)d_in[6];
    const float* Wout    = (const float*)d_in[7];
    const float* bout    = (const float*)d_in[8];
    float* out = (float*)d_out;

    const int SM128 = 2 * (128 * 128 + 128 * 128);   // 65536 bytes
    const int SM64  = 2 * (128 * 128 +  64 * 128);   // 49152 bytes
    cudaFuncSetAttribute(mixsoftmax_kernel, cudaFuncAttributeMaxDynamicSharedMemorySize, NH * SEQ * 4);
    cudaFuncSetAttribute(proj_k, cudaFuncAttributeMaxDynamicSharedMemorySize, SM128);
    cudaFuncSetAttribute(qk_k,   cudaFuncAttributeMaxDynamicSharedMemorySize, SM128);
    cudaFuncSetAttribute(av_k,   cudaFuncAttributeMaxDynamicSharedMemorySize, SM64);
    cudaFuncSetAttribute(out_k,  cudaFuncAttributeMaxDynamicSharedMemorySize, SM128);

    __half* d_wqt;  __half* d_wkvt;  __half* d_woutt;
    cudaGetSymbolAddress((void**)&d_wqt,   g_wqth);
    cudaGetSymbolAddress((void**)&d_wkvt,  g_wkvth);
    cudaGetSymbolAddress((void**)&d_woutt, g_woutth);

    dim3 tb(32, 8);
    ln_kernel<<<NROWS, 256>>>(x, ln_g, ln_b);
    wt_kernel<<<dim3(32, 32), tb>>>(Wq,   d_wqt,   DIMC, DIMC);
    wt_kernel<<<dim3(64, 32), tb>>>(Wkv,  d_wkvt,  DIMC, 2 * DIMC);
    wt_kernel<<<dim3(32, 32), tb>>>(Wout, d_woutt, DIMC, DIMC);
    proj_k<<<dim3(24, 32), 256, SM128>>>();
    vt_kernel<<<dim3(2, 64, 32), tb>>>();
    qk_k<<<dim3(16, 16, 32), 256, SM128>>>();
    mixsoftmax_kernel<<<BQ * SEQ, 256, NH * SEQ * 4>>>(mixpre, mixpost);
    av_k<<<dim3(16, 32), 256, SM64>>>();
    out_k<<<dim3(8, 32), 256, SM128>>>(bout, out);
}

// round 6
// speedup vs baseline: 1.5581x; 1.5581x over previous
#include <cuda_runtime.h>
#include <cstdint>

#define BQ   2
#define SEQ  2048
#define DIMC 1024
#define NH   16
#define DH   64
#define QKVC 3072
#define NROWS (BQ*SEQ)

// ---- device scratch ----
__device__ float g_xn[(size_t)NROWS * DIMC];
__device__ float g_qkv[(size_t)NROWS * QKVC];           // [q*0.125 | k | v] tf32-rounded
__device__ float g_dots[(size_t)BQ * NH * SEQ * SEQ];   // dots then probs
__device__ float g_ao[(size_t)BQ * NH * SEQ * DH];      // [b,g,i,d]
__device__ float g_wqt[(size_t)DIMC * DIMC];            // Wq^T  [n][k]
__device__ float g_wkvt[(size_t)2 * DIMC * DIMC];       // Wkv^T [n][k]
__device__ float g_woutt[(size_t)DIMC * DIMC];          // Wout^T[n][k]
__device__ float g_vt[(size_t)BQ * NH * DH * SEQ];      // V^T per (b,g): [d][j]

__device__ __forceinline__ float tf32r(float x) {
    uint32_t u; asm("cvt.rna.tf32.f32 %0, %1;" : "=r"(u) : "f"(x));
    return __uint_as_float(u);
}

#define MMA_TF32(c, a, b) \
    asm volatile("mma.sync.aligned.m16n8k8.row.col.f32.tf32.tf32.f32 " \
        "{%0,%1,%2,%3}, {%4,%5,%6,%7}, {%8,%9}, {%0,%1,%2,%3};" \
        : "+f"((c)[0]), "+f"((c)[1]), "+f"((c)[2]), "+f"((c)[3]) \
        : "r"((a)[0]), "r"((a)[1]), "r"((a)[2]), "r"((a)[3]), \
          "r"((b)[0]), "r"((b)[1]))

#define WIDX(m,k) (((m)*32) + (((((k)>>2)&7)^((m)&7))<<2) + ((k)&3))

// ============================================================ tf32 MMA engine (R4, unchanged)
template<int BN, int MT, bool APL>
__device__ __forceinline__ void gemm_core(
    const float* __restrict__ A, int lda, int aplane,
    const float* __restrict__ Bt, int ldb,
    float* __restrict__ C, int ldc, int KB,
    float cscale, int doRound, const float* __restrict__ bias)
{
    extern __shared__ float sm[];
    constexpr int ASZ = 128 * 32;
    constexpr int BSZ = BN * 32;
    constexpr int NT  = 4;
    constexpr int BCH = (BN == 128) ? 4 : 2;
    constexpr int BST = (BN == 128) ? 8 : 16;

    int t = threadIdx.x, lane = t & 31, w = t >> 5;
    int wm = (BN == 128) ? (w & 1) * 64 : (w & 3) * 32;
    int wn = (BN == 128) ? (w >> 1) * 32 : (w >> 2) * 32;

    int am = t >> 1, ak = (t & 1) * 4;
    int bn_ = (BN == 128) ? (t >> 1) : (t >> 2);
    int bk  = (BN == 128) ? (t & 1) * 4 : (t & 3) * 4;

    const float* Arow = A + (size_t)am * lda;
    const float* Brow = Bt + (size_t)bn_ * ldb;

    float4 aR[4], bR[BCH];
    float acc[MT][NT][4];
    #pragma unroll
    for (int mt = 0; mt < MT; mt++)
        #pragma unroll
        for (int nt = 0; nt < NT; nt++)
            #pragma unroll
            for (int i = 0; i < 4; i++) acc[mt][nt][i] = 0.f;

    {
        #pragma unroll
        for (int c = 0; c < 4; c++) {
            int k = ak + c * 8;
            size_t off = APL ? ((size_t)(k >> 6) * aplane + (k & 63)) : (size_t)k;
            aR[c] = *(const float4*)(Arow + off);
        }
        #pragma unroll
        for (int c = 0; c < BCH; c++) bR[c] = *(const float4*)(Brow + bk + c * BST);
        float* sA = sm;
        float* sB = sm + ASZ;
        #pragma unroll
        for (int c = 0; c < 4; c++) {
            int k = ak + c * 8;
            *(float4*)&sA[(am * 32) + (((((k >> 2) & 7) ^ (am & 7))) << 2)] = aR[c];
        }
        #pragma unroll
        for (int c = 0; c < BCH; c++) {
            int k = bk + c * BST;
            *(float4*)&sB[(bn_ * 32) + (((((k >> 2) & 7) ^ (bn_ & 7))) << 2)] = bR[c];
        }
    }
    __syncthreads();

    int stage = 0;
    int lm = lane >> 2, lk = lane & 3;
    for (int kb = 0; kb < KB; kb++) {
        bool more = (kb + 1 < KB);
        if (more) {
            int kbase = (kb + 1) * 32;
            #pragma unroll
            for (int c = 0; c < 4; c++) {
                int k = kbase + ak + c * 8;
                size_t off = APL ? ((size_t)(k >> 6) * aplane + (k & 63)) : (size_t)k;
                aR[c] = *(const float4*)(Arow + off);
            }
            #pragma unroll
            for (int c = 0; c < BCH; c++)
                bR[c] = *(const float4*)(Brow + kbase + bk + c * BST);
        }
        const float* sA = sm + stage * (ASZ + BSZ);
        const float* sB = sA + ASZ;
        #pragma unroll
        for (int ks = 0; ks < 4; ks++) {
            int k0 = ks * 8 + lk;
            uint32_t af[MT][4], bf[NT][2];
            #pragma unroll
            for (int mt = 0; mt < MT; mt++) {
                int m1 = wm + mt * 16 + lm;
                af[mt][0] = __float_as_uint(sA[WIDX(m1,     k0)]);
                af[mt][1] = __float_as_uint(sA[WIDX(m1 + 8, k0)]);
                af[mt][2] = __float_as_uint(sA[WIDX(m1,     k0 + 4)]);
                af[mt][3] = __float_as_uint(sA[WIDX(m1 + 8, k0 + 4)]);
            }
            #pragma unroll
            for (int nt = 0; nt < NT; nt++) {
                int n1 = wn + nt * 8 + lm;
                bf[nt][0] = __float_as_uint(sB[WIDX(n1, k0)]);
                bf[nt][1] = __float_as_uint(sB[WIDX(n1, k0 + 4)]);
            }
            #pragma unroll
            for (int mt = 0; mt < MT; mt++)
                #pragma unroll
                for (int nt = 0; nt < NT; nt++)
                    MMA_TF32(acc[mt][nt], af[mt], bf[nt]);
        }
        if (more) {
            float* dA = sm + (stage ^ 1) * (ASZ + BSZ);
            float* dB = dA + ASZ;
            #pragma unroll
            for (int c = 0; c < 4; c++) {
                int k = ak + c * 8;
                *(float4*)&dA[(am * 32) + (((((k >> 2) & 7) ^ (am & 7))) << 2)] = aR[c];
            }
            #pragma unroll
            for (int c = 0; c < BCH; c++) {
                int k = bk + c * BST;
                *(float4*)&dB[(bn_ * 32) + (((((k >> 2) & 7) ^ (bn_ & 7))) << 2)] = bR[c];
            }
            __syncthreads();
            stage ^= 1;
        }
    }

    #pragma unroll
    for (int mt = 0; mt < MT; mt++) {
        int r0 = wm + mt * 16 + (lane >> 2);
        #pragma unroll
        for (int nt = 0; nt < NT; nt++) {
            int c0 = wn + nt * 8 + 2 * (lane & 3);
            float v0 = acc[mt][nt][0] * cscale, v1 = acc[mt][nt][1] * cscale;
            float v2 = acc[mt][nt][2] * cscale, v3 = acc[mt][nt][3] * cscale;
            if (doRound) { v0 = tf32r(v0); v1 = tf32r(v1); v2 = tf32r(v2); v3 = tf32r(v3); }
            if (bias) {
                float b0 = bias[c0], b1 = bias[c0 + 1];
                v0 += b0; v1 += b1; v2 += b0; v3 += b1;
            }
            *(float2*)&C[(size_t)r0 * ldc + c0]       = make_float2(v0, v1);
            *(float2*)&C[(size_t)(r0 + 8) * ldc + c0] = make_float2(v2, v3);
        }
    }
}

// ============================================================ FFMA SIMT engine
// C[128x128] = A[128xK] @ Bt[128xK]^T, 256 thr, 8x8/thread, BK=16
__device__ __forceinline__ void fgemm_128(
    const float* __restrict__ A, int lda, size_t aplane, int apl,
    const float* __restrict__ Bt, int ldb,
    float* __restrict__ C, int ldc, int KB,
    float cscale, int doRound, const float* __restrict__ bias)
{
    __shared__ float As[16][128];
    __shared__ float Bs[16][128];
    int t = threadIdx.x;
    int ar = t >> 1, ac = (t & 1) * 8;
    int tx = t & 15, ty = t >> 4;
    float acc[8][8];
    #pragma unroll
    for (int i = 0; i < 8; i++)
        #pragma unroll
        for (int j = 0; j < 8; j++) acc[i][j] = 0.f;
    const float* Ab = A + (size_t)ar * lda;
    const float* Bb = Bt + (size_t)ar * ldb;
    for (int kb = 0; kb < KB; kb++) {
        int k0 = kb * 16 + ac;
        float4 a0, a1;
        if (apl) {
            a0 = *(const float4*)(Ab + (size_t)(k0 >> 6) * aplane + (k0 & 63));
            int k4 = k0 + 4;
            a1 = *(const float4*)(Ab + (size_t)(k4 >> 6) * aplane + (k4 & 63));
        } else {
            a0 = *(const float4*)(Ab + k0);
            a1 = *(const float4*)(Ab + k0 + 4);
        }
        float4 b0 = *(const float4*)(Bb + k0);
        float4 b1 = *(const float4*)(Bb + k0 + 4);
        __syncthreads();
        As[ac+0][ar] = a0.x; As[ac+1][ar] = a0.y; As[ac+2][ar] = a0.z; As[ac+3][ar] = a0.w;
        As[ac+4][ar] = a1.x; As[ac+5][ar] = a1.y; As[ac+6][ar] = a1.z; As[ac+7][ar] = a1.w;
        Bs[ac+0][ar] = b0.x; Bs[ac+1][ar] = b0.y; Bs[ac+2][ar] = b0.z; Bs[ac+3][ar] = b0.w;
        Bs[ac+4][ar] = b1.x; Bs[ac+5][ar] = b1.y; Bs[ac+6][ar] = b1.z; Bs[ac+7][ar] = b1.w;
        __syncthreads();
        #pragma unroll
        for (int k = 0; k < 16; k++) {
            float rm[8], rn[8];
            *(float4*)&rm[0] = *(const float4*)&As[k][ty*8];
            *(float4*)&rm[4] = *(const float4*)&As[k][ty*8+4];
            *(float4*)&rn[0] = *(const float4*)&Bs[k][tx*8];
            *(float4*)&rn[4] = *(const float4*)&Bs[k][tx*8+4];
            #pragma unroll
            for (int i = 0; i < 8; i++)
                #pragma unroll
                for (int j = 0; j < 8; j++)
                    acc[i][j] = fmaf(rm[i], rn[j], acc[i][j]);
        }
    }
    #pragma unroll
    for (int i = 0; i < 8; i++) {
        int r0 = ty * 8 + i;
        #pragma unroll
        for (int j = 0; j < 8; j += 2) {
            int c0 = tx * 8 + j;
            float v0 = acc[i][j] * cscale, v1 = acc[i][j+1] * cscale;
            if (doRound) { v0 = tf32r(v0); v1 = tf32r(v1); }
            if (bias) { v0 += bias[c0]; v1 += bias[c0 + 1]; }
            *(float2*)&C[(size_t)r0 * ldc + c0] = make_float2(v0, v1);
        }
    }
}

// C[128x64] variant (av): 4x8/thread
__device__ __forceinline__ void fgemm_64(
    const float* __restrict__ A, int lda,
    const float* __restrict__ Bt, int ldb,
    float* __restrict__ C, int ldc, int KB)
{
    __shared__ float As[16][128];
    __shared__ float Bs[16][64];
    int t = threadIdx.x;
    int ar = t >> 1, ac = (t & 1) * 8;
    int bn = t >> 2, bk = (t & 3) * 4;
    int tx = t & 7, ty = t >> 3;
    float acc[4][8];
    #pragma unroll
    for (int i = 0; i < 4; i++)
        #pragma unroll
        for (int j = 0; j < 8; j++) acc[i][j] = 0.f;
    const float* Ab = A + (size_t)ar * lda;
    const float* Bb = Bt + (size_t)bn * ldb;
    for (int kb = 0; kb < KB; kb++) {
        int k0 = kb * 16 + ac;
        float4 a0 = *(const float4*)(Ab + k0);
        float4 a1 = *(const float4*)(Ab + k0 + 4);
        float4 b0 = *(const float4*)(Bb + kb * 16 + bk);
        __syncthreads();
        As[ac+0][ar] = a0.x; As[ac+1][ar] = a0.y; As[ac+2][ar] = a0.z; As[ac+3][ar] = a0.w;
        As[ac+4][ar] = a1.x; As[ac+5][ar] = a1.y; As[ac+6][ar] = a1.z; As[ac+7][ar] = a1.w;
        Bs[bk+0][bn] = b0.x; Bs[bk+1][bn] = b0.y; Bs[bk+2][bn] = b0.z; Bs[bk+3][bn] = b0.w;
        __syncthreads();
        #pragma unroll
        for (int k = 0; k < 16; k++) {
            float rm[4], rn[8];
            *(float4*)&rm[0] = *(const float4*)&As[k][ty*4];
            *(float4*)&rn[0] = *(const float4*)&Bs[k][tx*8];
            *(float4*)&rn[4] = *(const float4*)&Bs[k][tx*8+4];
            #pragma unroll
            for (int i = 0; i < 4; i++)
                #pragma unroll
                for (int j = 0; j < 8; j++)
                    acc[i][j] = fmaf(rm[i], rn[j], acc[i][j]);
        }
    }
    #pragma unroll
    for (int i = 0; i < 4; i++) {
        int r0 = ty * 4 + i;
        #pragma unroll
        for (int j = 0; j < 8; j += 2) {
            int c0 = tx * 8 + j;
            *(float2*)&C[(size_t)r0 * ldc + c0] =
                make_float2(tf32r(acc[i][j]), tf32r(acc[i][j+1]));
        }
    }
}

// ============================================================ LayerNorm
__global__ void ln_kernel(const float* __restrict__ x,
                          const float* __restrict__ gamma,
                          const float* __restrict__ beta) {
    int row = blockIdx.x;
    int t = threadIdx.x;
    const float4* xr = (const float4*)(x + (size_t)row * DIMC);
    float4 v = xr[t];
    float s = v.x + v.y + v.z + v.w;
    float q = v.x*v.x + v.y*v.y + v.z*v.z + v.w*v.w;
    __shared__ float s_sum[8], s_sq[8];
    #pragma unroll
    for (int o = 16; o > 0; o >>= 1) {
        s += __shfl_xor_sync(0xffffffffu, s, o);
        q += __shfl_xor_sync(0xffffffffu, q, o);
    }
    if ((t & 31) == 0) { s_sum[t >> 5] = s; s_sq[t >> 5] = q; }
    __syncthreads();
    if (t < 32) {
        float a = (t < 8) ? s_sum[t] : 0.f;
        float c = (t < 8) ? s_sq[t] : 0.f;
        #pragma unroll
        for (int o = 4; o > 0; o >>= 1) {
            a += __shfl_xor_sync(0xffffffffu, a, o);
            c += __shfl_xor_sync(0xffffffffu, c, o);
        }
        if (t == 0) { s_sum[0] = a; s_sq[0] = c; }
    }
    __syncthreads();
    float mean = s_sum[0] * (1.f / DIMC);
    float var  = s_sq[0] * (1.f / DIMC) - mean * mean;
    float rs = rsqrtf(var + 1e-5f);
    float4 gg = ((const float4*)gamma)[t];
    float4 bb = ((const float4*)beta)[t];
    float4 o;
    o.x = tf32r((v.x - mean) * rs * gg.x + bb.x);
    o.y = tf32r((v.y - mean) * rs * gg.y + bb.y);
    o.z = tf32r((v.z - mean) * rs * gg.z + bb.z);
    o.w = tf32r((v.w - mean) * rs * gg.w + bb.w);
    ((float4*)(g_xn + (size_t)row * DIMC))[t] = o;
}

// ============================================================ transposes
__global__ void wt_kernel(const float* __restrict__ src, float* __restrict__ dst,
                          int R, int C) {
    __shared__ float tile[32][33];
    int tx = threadIdx.x, ty = threadIdx.y;
    int c0 = blockIdx.x * 32, r0 = blockIdx.y * 32;
    #pragma unroll
    for (int i = 0; i < 32; i += 8)
        tile[ty + i][tx] = tf32r(src[(size_t)(r0 + ty + i) * C + c0 + tx]);
    __syncthreads();
    #pragma unroll
    for (int i = 0; i < 32; i += 8)
        dst[(size_t)(c0 + ty + i) * R + r0 + tx] = tile[tx][ty + i];
}

__global__ void vt_kernel() {
    __shared__ float tile[32][33];
    int tx = threadIdx.x, ty = threadIdx.y;
    int z = blockIdx.z, b = z >> 4, g = z & 15;
    int d0 = blockIdx.x * 32, i0 = blockIdx.y * 32;
    const float* src = g_qkv + (size_t)b * SEQ * QKVC + 2048 + g * 64;
    #pragma unroll
    for (int i = 0; i < 32; i += 8)
        tile[ty + i][tx] = src[(size_t)(i0 + ty + i) * QKVC + d0 + tx];
    __syncthreads();
    float* dst = g_vt + (size_t)z * DH * SEQ;
    #pragma unroll
    for (int i = 0; i < 32; i += 8)
        dst[(size_t)(d0 + ty + i) * SEQ + i0 + tx] = tile[tx][ty + i];
}

// ============================================================ GEMM wrappers (split tiles)
__global__ __launch_bounds__(256) void proj_k() {              // tiles 0..15
    int m0 = blockIdx.y * 128, cb = blockIdx.x * 128;
    const float* Bt = (cb < 1024) ? (g_wqt + (size_t)cb * DIMC)
                                  : (g_wkvt + (size_t)(cb - 1024) * DIMC);
    gemm_core<128, 4, false>(g_xn + (size_t)m0 * DIMC, DIMC, 0, Bt, DIMC,
                             g_qkv + (size_t)m0 * QKVC + cb, QKVC, DIMC / 32,
                             (cb < 1024) ? 0.125f : 1.0f, 1, nullptr);
}
__global__ __launch_bounds__(256) void proj_f() {              // tiles 16..23
    int m0 = blockIdx.y * 128, cb = (16 + blockIdx.x) * 128;
    const float* Bt = (cb < 1024) ? (g_wqt + (size_t)cb * DIMC)
                                  : (g_wkvt + (size_t)(cb - 1024) * DIMC);
    fgemm_128(g_xn + (size_t)m0 * DIMC, DIMC, 0, 0, Bt, DIMC,
              g_qkv + (size_t)m0 * QKVC + cb, QKVC, DIMC / 16,
              (cb < 1024) ? 0.125f : 1.0f, 1, nullptr);
}

__global__ __launch_bounds__(256) void qk_k(int b) {           // n-tiles 0..10
    int z = b * 16 + blockIdx.z;
    int m0 = blockIdx.y * 128, n0 = blockIdx.x * 128;
    const float* base = g_qkv + (size_t)b * SEQ * QKVC;
    gemm_core<128, 4, false>(base + (size_t)m0 * QKVC + (blockIdx.z) * DH, QKVC, 0,
                             base + (size_t)n0 * QKVC + 1024 + (blockIdx.z) * DH, QKVC,
                             g_dots + ((size_t)z * SEQ + m0) * SEQ + n0, SEQ, DH / 32,
                             1.0f, 0, nullptr);
}
__global__ __launch_bounds__(256) void qk_f(int b) {           // n-tiles 11..15
    int h = blockIdx.z, z = b * 16 + h;
    int m0 = blockIdx.y * 128, n0 = (11 + blockIdx.x) * 128;
    const float* base = g_qkv + (size_t)b * SEQ * QKVC;
    fgemm_128(base + (size_t)m0 * QKVC + h * DH, QKVC, 0, 0,
              base + (size_t)n0 * QKVC + 1024 + h * DH, QKVC,
              g_dots + ((size_t)z * SEQ + m0) * SEQ + n0, SEQ, DH / 16,
              1.0f, 0, nullptr);
}

__global__ __launch_bounds__(256) void av_k(int b) {           // m-tiles 0..10
    int z = b * 16 + blockIdx.y, m0 = blockIdx.x * 128;
    gemm_core<64, 2, false>(g_dots + (size_t)z * SEQ * SEQ + (size_t)m0 * SEQ, SEQ, 0,
                            g_vt + (size_t)z * DH * SEQ, SEQ,
                            g_ao + ((size_t)z * SEQ + m0) * DH, DH, SEQ / 32,
                            1.0f, 1, nullptr);
}
__global__ __launch_bounds__(256) void av_f(int b) {           // m-tiles 11..15
    int z = b * 16 + blockIdx.y, m0 = (11 + blockIdx.x) * 128;
    fgemm_64(g_dots + (size_t)z * SEQ * SEQ + (size_t)m0 * SEQ, SEQ,
             g_vt + (size_t)z * DH * SEQ, SEQ,
             g_ao + ((size_t)z * SEQ + m0) * DH, DH, SEQ / 16);
}

__global__ __launch_bounds__(256) void out_k(const float* __restrict__ bout,
                                             float* __restrict__ out) {   // n-tiles 0..4
    int m0 = blockIdx.y * 128, n0 = blockIdx.x * 128;
    int b = m0 >> 11, i0 = m0 & (SEQ - 1);
    gemm_core<128, 4, true>(g_ao + ((size_t)(b * NH) * SEQ + i0) * DH, DH, SEQ * DH,
                            g_woutt + (size_t)n0 * DIMC, DIMC,
                            out + (size_t)m0 * DIMC + n0, DIMC, DIMC / 32,
                            1.0f, 0, bout + n0);
}
__global__ __launch_bounds__(256) void out_f(const float* __restrict__ bout,
                                             float* __restrict__ out) {   // n-tiles 5..7
    int m0 = blockIdx.y * 128, n0 = (5 + blockIdx.x) * 128;
    int b = m0 >> 11, i0 = m0 & (SEQ - 1);
    fgemm_128(g_ao + ((size_t)(b * NH) * SEQ + i0) * DH, DH, (size_t)SEQ * DH, 1,
              g_woutt + (size_t)n0 * DIMC, DIMC,
              out + (size_t)m0 * DIMC + n0, DIMC, DIMC / 16,
              1.0f, 0, bout + n0);
}

// ============================================================ mix -> softmax -> mix (i-range split)
__global__ __launch_bounds__(256)
void mixsoftmax_kernel(const float* __restrict__ mix_pre, const float* __restrict__ mix_post,
                       int b, int iOff) {
    extern __shared__ float srow[];
    __shared__ float mp[256], mq[256];
    __shared__ float red[NH][8];
    __shared__ float mg[NH], linv[NH];
    int t = threadIdx.x;
    int i = iOff + blockIdx.x;
    mp[t] = mix_pre[t];
    mq[t] = mix_post[t];
    size_t base = ((size_t)(b * NH) * SEQ + i) * SEQ;
    for (int h = 0; h < NH; h++) {
        const float4* src = (const float4*)(g_dots + base + (size_t)h * SEQ * SEQ);
        float4* dst = (float4*)(srow + h * SEQ);
        for (int j = t; j < SEQ/4; j += 256) dst[j] = src[j];
    }
    __syncthreads();
    float tmax[NH];
    #pragma unroll
    for (int g = 0; g < NH; g++) tmax[g] = -3.4e38f;
    for (int j = t; j < SEQ; j += 256) {
        float sh[NH];
        #pragma unroll
        for (int h = 0; h < NH; h++) sh[h] = srow[h*SEQ + j];
        #pragma unroll
        for (int g = 0; g < NH; g++) {
            float v = 0.f;
            #pragma unroll
            for (int h = 0; h < NH; h++) v = fmaf(mp[h*NH + g], sh[h], v);
            srow[g*SEQ + j] = v;
            tmax[g] = fmaxf(tmax[g], v);
        }
    }
    int w = t >> 5, l = t & 31;
    #pragma unroll
    for (int g = 0; g < NH; g++) {
        float v = tmax[g];
        #pragma unroll
        for (int o = 16; o > 0; o >>= 1) v = fmaxf(v, __shfl_xor_sync(0xffffffffu, v, o));
        if (l == 0) red[g][w] = v;
    }
    __syncthreads();
    if (t < NH) {
        float v = red[t][0];
        #pragma unroll
        for (int w2 = 1; w2 < 8; w2++) v = fmaxf(v, red[t][w2]);
        mg[t] = v;
    }
    __syncthreads();
    float tsum[NH];
    #pragma unroll
    for (int g = 0; g < NH; g++) tsum[g] = 0.f;
    for (int j = t; j < SEQ; j += 256) {
        #pragma unroll
        for (int g = 0; g < NH; g++) {
            float e = __expf(srow[g*SEQ + j] - mg[g]);
            srow[g*SEQ + j] = e;
            tsum[g] += e;
        }
    }
    __syncthreads();
    #pragma unroll
    for (int g = 0; g < NH; g++) {
        float v = tsum[g];
        #pragma unroll
        for (int o = 16; o > 0; o >>= 1) v += __shfl_xor_sync(0xffffffffu, v, o);
        if (l == 0) red[g][w] = v;
    }
    __syncthreads();
    if (t < NH) {
        float v = 0.f;
        #pragma unroll
        for (int w2 = 0; w2 < 8; w2++) v += red[t][w2];
        linv[t] = 1.f / v;
    }
    __syncthreads();
    for (int j = t; j < SEQ; j += 256) {
        float ph[NH];
        #pragma unroll
        for (int h = 0; h < NH; h++) ph[h] = srow[h*SEQ + j] * linv[h];
        #pragma unroll
        for (int g = 0; g < NH; g++) {
            float v = 0.f;
            #pragma unroll
            for (int h = 0; h < NH; h++) v = fmaf(mq[h*NH + g], ph[h], v);
            g_dots[base + (size_t)g*SEQ*SEQ + j] = tf32r(v);
        }
    }
}

// ============================================================ launch: 2-stream fork-join pipeline
extern "C" void kernel_launch(void* const* d_in, const int* in_sizes, int n_in,
                              void* d_out, int out_size) {
    const float* x       = (const float*)d_in[0];
    const float* ln_g    = (const float*)d_in[1];
    const float* ln_b    = (const float*)d_in[2];
    const float* Wq      = (const float*)d_in[3];
    const float* Wkv     = (const float*)d_in[4];
    const float* mixpre  = (const float*)d_in[5];
    const float* mixpost = (const float*)d_in[6];
    const float* Wout    = (const float*)d_in[7];
    const float* bout    = (const float*)d_in[8];
    float* out = (float*)d_out;

    const int SM128 = 2 * (128*32 + 128*32) * 4;
    const int SM64  = 2 * (128*32 +  64*32) * 4;
    static bool init0 = false;
    static cudaStream_t s1;
    static cudaEvent_t evRoot, evWt, evLn, evPm, evPf, evQm0, evQm1, evQf0, evQf1,
                       evMa0, evMa1, evMb0, evMb1, evAm, evAf, evOf;
    if (!init0) {
        cudaStreamCreateWithFlags(&s1, cudaStreamNonBlocking);
        cudaEvent_t* evs[] = {&evRoot,&evWt,&evLn,&evPm,&evPf,&evQm0,&evQm1,&evQf0,&evQf1,
                              &evMa0,&evMa1,&evMb0,&evMb1,&evAm,&evAf,&evOf};
        for (auto e : evs) cudaEventCreateWithFlags(e, cudaEventDisableTiming);
        cudaFuncSetAttribute(mixsoftmax_kernel, cudaFuncAttributeMaxDynamicSharedMemorySize, NH*SEQ*4);
        cudaFuncSetAttribute(proj_k, cudaFuncAttributeMaxDynamicSharedMemorySize, SM128);
        cudaFuncSetAttribute(qk_k,   cudaFuncAttributeMaxDynamicSharedMemorySize, SM128);
        cudaFuncSetAttribute(av_k,   cudaFuncAttributeMaxDynamicSharedMemorySize, SM64);
        cudaFuncSetAttribute(out_k,  cudaFuncAttributeMaxDynamicSharedMemorySize, SM128);
        init0 = true;
    }

    float *d_wqt, *d_wkvt, *d_woutt;
    cudaGetSymbolAddress((void**)&d_wqt,   g_wqt);
    cudaGetSymbolAddress((void**)&d_wkvt,  g_wkvt);
    cudaGetSymbolAddress((void**)&d_woutt, g_woutt);

    dim3 tb(32, 8);

    // ---- fork s1 from capture stream ----
    cudaEventRecord(evRoot, 0);
    cudaStreamWaitEvent(s1, evRoot, 0);

    // stage 0: LN (s0) || weight transposes (s1)
    ln_kernel<<<NROWS, 256>>>(x, ln_g, ln_b);
    cudaEventRecord(evLn, 0);
    wt_kernel<<<dim3(32, 32), tb, 0, s1>>>(Wq,   d_wqt,   DIMC, DIMC);
    wt_kernel<<<dim3(64, 32), tb, 0, s1>>>(Wkv,  d_wkvt,  DIMC, 2 * DIMC);
    wt_kernel<<<dim3(32, 32), tb, 0, s1>>>(Wout, d_woutt, DIMC, DIMC);
    cudaEventRecord(evWt, s1);

    // stage 1: proj split
    cudaStreamWaitEvent(0, evWt, 0);
    proj_k<<<dim3(16, 32), 256, SM128>>>();
    cudaEventRecord(evPm, 0);
    cudaStreamWaitEvent(s1, evLn, 0);
    proj_f<<<dim3(8, 32), 256, 0, s1>>>();
    cudaEventRecord(evPf, s1);

    // stage 2: qk split + vt
    cudaStreamWaitEvent(0, evPf, 0);
    qk_k<<<dim3(11, 16, 16), 256, SM128>>>(0);
    cudaEventRecord(evQm0, 0);
    qk_k<<<dim3(11, 16, 16), 256, SM128>>>(1);
    cudaEventRecord(evQm1, 0);
    cudaStreamWaitEvent(s1, evPm, 0);
    vt_kernel<<<dim3(2, 64, 32), tb, 0, s1>>>();
    qk_f<<<dim3(5, 16, 16), 256, 0, s1>>>(0);
    cudaEventRecord(evQf0, s1);
    qk_f<<<dim3(5, 16, 16), 256, 0, s1>>>(1);
    cudaEventRecord(evQf1, s1);

    // stage 3: mixsoftmax, i-halves split across streams
    cudaStreamWaitEvent(0, evQf0, 0);
    mixsoftmax_kernel<<<1024, 256, NH*SEQ*4>>>(mixpre, mixpost, 0, 0);
    cudaEventRecord(evMa0, 0);
    cudaStreamWaitEvent(0, evQf1, 0);
    mixsoftmax_kernel<<<1024, 256, NH*SEQ*4>>>(mixpre, mixpost, 1, 0);
    cudaEventRecord(evMa1, 0);
    cudaStreamWaitEvent(s1, evQm0, 0);
    mixsoftmax_kernel<<<1024, 256, NH*SEQ*4, s1>>>(mixpre, mixpost, 0, 1024);
    cudaEventRecord(evMb0, s1);
    cudaStreamWaitEvent(s1, evQm1, 0);
    mixsoftmax_kernel<<<1024, 256, NH*SEQ*4, s1>>>(mixpre, mixpost, 1, 1024);
    cudaEventRecord(evMb1, s1);

    // stage 4: av split (needs both mix halves of its batch; vt via s1 ordering)
    cudaStreamWaitEvent(0, evMb0, 0);
    av_k<<<dim3(11, 16), 256, SM64>>>(0);
    cudaStreamWaitEvent(0, evMb1, 0);
    av_k<<<dim3(11, 16), 256, SM64>>>(1);
    cudaEventRecord(evAm, 0);
    cudaStreamWaitEvent(s1, evMa0, 0);
    av_f<<<dim3(5, 16), 256, 0, s1>>>(0);
    cudaStreamWaitEvent(s1, evMa1, 0);
    av_f<<<dim3(5, 16), 256, 0, s1>>>(1);
    cudaEventRecord(evAf, s1);

    // stage 5: out split (needs all av)
    cudaStreamWaitEvent(0, evAf, 0);
    out_k<<<dim3(5, 32), 256, SM128>>>(bout, out);
    cudaStreamWaitEvent(s1, evAm, 0);
    out_f<<<dim3(3, 32), 256, 0, s1>>>(bout, out);
    cudaEventRecord(evOf, s1);

    // ---- join ----
    cudaStreamWaitEvent(0, evOf, 0);
}

// round 7
// speedup vs baseline: 2.0585x; 1.3212x over previous
#include <cuda_runtime.h>
#include <cstdint>

#define BQ   2
#define SEQ  2048
#define DIMC 1024
#define NH   16
#define DH   64
#define QKVC 3072
#define NROWS (BQ*SEQ)

// ---- device scratch ----
__device__ float g_xn[(size_t)NROWS * DIMC];            // 16 MB
__device__ float g_qkv[(size_t)NROWS * QKVC];           // 48 MB  [q | k | v]
__device__ float g_dots[(size_t)BQ * NH * SEQ * SEQ];   // 512 MB
__device__ float g_ao[(size_t)BQ * NH * SEQ * DH];      // 16 MB  [b,g,i,d]

__device__ __forceinline__ uint32_t f2tf32(float f) {
    uint32_t u; asm("cvt.rna.tf32.f32 %0, %1;" : "=r"(u) : "f"(f)); return u;
}

#define MMA_TF32(c, a, b) \
    asm volatile("mma.sync.aligned.m16n8k8.row.col.f32.tf32.tf32.f32 " \
        "{%0,%1,%2,%3}, {%4,%5,%6,%7}, {%8,%9}, {%0,%1,%2,%3};" \
        : "+f"((c)[0]), "+f"((c)[1]), "+f"((c)[2]), "+f"((c)[3]) \
        : "r"((a)[0]), "r"((a)[1]), "r"((a)[2]), "r"((a)[3]), \
          "r"((b)[0]), "r"((b)[1]))

// ============================================================ LayerNorm
__global__ void ln_kernel(const float* __restrict__ x,
                          const float* __restrict__ gamma,
                          const float* __restrict__ beta) {
    int row = blockIdx.x;
    int t = threadIdx.x;
    const float4* xr = (const float4*)(x + (size_t)row * DIMC);
    float4 v = xr[t];
    float s = v.x + v.y + v.z + v.w;
    float q = v.x*v.x + v.y*v.y + v.z*v.z + v.w*v.w;
    __shared__ float s_sum[8], s_sq[8];
    #pragma unroll
    for (int o = 16; o > 0; o >>= 1) {
        s += __shfl_xor_sync(0xffffffffu, s, o);
        q += __shfl_xor_sync(0xffffffffu, q, o);
    }
    if ((t & 31) == 0) { s_sum[t >> 5] = s; s_sq[t >> 5] = q; }
    __syncthreads();
    if (t < 32) {
        float a = (t < 8) ? s_sum[t] : 0.f;
        float c = (t < 8) ? s_sq[t] : 0.f;
        #pragma unroll
        for (int o = 4; o > 0; o >>= 1) {
            a += __shfl_xor_sync(0xffffffffu, a, o);
            c += __shfl_xor_sync(0xffffffffu, c, o);
        }
        if (t == 0) { s_sum[0] = a; s_sq[0] = c; }
    }
    __syncthreads();
    float mean = s_sum[0] * (1.f / DIMC);
    float var  = s_sq[0] * (1.f / DIMC) - mean * mean;
    float rs = rsqrtf(var + 1e-5f);
    float4 gg = ((const float4*)gamma)[t];
    float4 bb = ((const float4*)beta)[t];
    float4 o;
    o.x = (v.x - mean) * rs * gg.x + bb.x;
    o.y = (v.y - mean) * rs * gg.y + bb.y;
    o.z = (v.z - mean) * rs * gg.z + bb.z;
    o.w = (v.w - mean) * rs * gg.w + bb.w;
    ((float4*)(g_xn + (size_t)row * DIMC))[t] = o;
}

// ============================================================ QKV projection (TF32 MMA)
__global__ __launch_bounds__(256)
void proj_mma_kernel(const float* __restrict__ Wq, const float* __restrict__ Wkv) {
    __shared__ uint32_t As[16][136];
    __shared__ uint32_t Bs[16][136];
    int t = threadIdx.x, lane = t & 31, w = t >> 5;
    int wm = (w & 1) * 64, wn = (w >> 1) * 32;
    int cb = blockIdx.x * 128;
    const float* Bp; int ldb;
    if (cb < 1024) { Bp = Wq; ldb = 1024; } else { Bp = Wkv; ldb = 2048; cb -= 1024; }
    int m0 = blockIdx.y * 128;
    int sa_m = t >> 1, sa_k = (t & 1) * 8;
    int sb_k = t >> 4, sb_n = (t & 15) * 8;
    const float* Aptr = g_xn + (size_t)(m0 + sa_m) * DIMC + sa_k;
    const float* Bptr = Bp + (size_t)sb_k * ldb + cb + sb_n;
    float c[4][4][4] = {};
    for (int kk = 0; kk < DIMC; kk += 16) {
        float4 a0 = *(const float4*)Aptr;
        float4 a1 = *(const float4*)(Aptr + 4);
        Aptr += 16;
        float4 b0 = *(const float4*)Bptr;
        float4 b1 = *(const float4*)(Bptr + 4);
        Bptr += (size_t)16 * ldb;
        As[sa_k+0][sa_m] = f2tf32(a0.x); As[sa_k+1][sa_m] = f2tf32(a0.y);
        As[sa_k+2][sa_m] = f2tf32(a0.z); As[sa_k+3][sa_m] = f2tf32(a0.w);
        As[sa_k+4][sa_m] = f2tf32(a1.x); As[sa_k+5][sa_m] = f2tf32(a1.y);
        As[sa_k+6][sa_m] = f2tf32(a1.z); As[sa_k+7][sa_m] = f2tf32(a1.w);
        *(uint4*)&Bs[sb_k][sb_n]   = make_uint4(f2tf32(b0.x), f2tf32(b0.y), f2tf32(b0.z), f2tf32(b0.w));
        *(uint4*)&Bs[sb_k][sb_n+4] = make_uint4(f2tf32(b1.x), f2tf32(b1.y), f2tf32(b1.z), f2tf32(b1.w));
        __syncthreads();
        #pragma unroll
        for (int ks = 0; ks < 2; ks++) {
            int kr = ks * 8 + (lane & 3);
            int mr = wm + (lane >> 2);
            int nr = wn + (lane >> 2);
            uint32_t af[4][4], bf[4][2];
            #pragma unroll
            for (int mt = 0; mt < 4; mt++) {
                af[mt][0] = As[kr][mr + mt*16];
                af[mt][1] = As[kr][mr + mt*16 + 8];
                af[mt][2] = As[kr+4][mr + mt*16];
                af[mt][3] = As[kr+4][mr + mt*16 + 8];
            }
            #pragma unroll
            for (int nt = 0; nt < 4; nt++) {
                bf[nt][0] = Bs[kr][nr + nt*8];
                bf[nt][1] = Bs[kr+4][nr + nt*8];
            }
            #pragma unroll
            for (int mt = 0; mt < 4; mt++)
                #pragma unroll
                for (int nt = 0; nt < 4; nt++)
                    MMA_TF32(c[mt][nt], af[mt], bf[nt]);
        }
        __syncthreads();
    }
    int col0 = blockIdx.x * 128 + wn + 2 * (lane & 3);
    int row0 = m0 + wm + (lane >> 2);
    #pragma unroll
    for (int mt = 0; mt < 4; mt++)
        #pragma unroll
        for (int nt = 0; nt < 4; nt++) {
            float* Cp = g_qkv + (size_t)(row0 + mt*16) * QKVC + col0 + nt*8;
            *(float2*)Cp = make_float2(c[mt][nt][0], c[mt][nt][1]);
            *(float2*)(Cp + (size_t)8 * QKVC) = make_float2(c[mt][nt][2], c[mt][nt][3]);
        }
}

// ============================================================ S_h = scale * Q_h K_h^T (per batch)
__global__ __launch_bounds__(256)
void qk_mma_kernel(int b) {
    __shared__ uint32_t As[16][136];
    __shared__ uint32_t Bs[16][136];
    int t = threadIdx.x, lane = t & 31, w = t >> 5;
    int wm = (w & 1) * 64, wn = (w >> 1) * 32;
    int h = blockIdx.z, z = b * 16 + h;
    const float* Qb = g_qkv + (size_t)b * SEQ * QKVC + h * DH;
    const float* Kb = Qb + 1024;
    int m0 = blockIdx.y * 128, n0 = blockIdx.x * 128;
    int sm = t >> 1, sk = (t & 1) * 8;
    const float* Ap  = Qb + (size_t)(m0 + sm) * QKVC + sk;
    const float* Bp  = Kb + (size_t)(n0 + sm) * QKVC + sk;
    float c[4][4][4] = {};
    for (int kk = 0; kk < DH; kk += 16) {
        float4 a0 = *(const float4*)Ap;
        float4 a1 = *(const float4*)(Ap + 4);
        Ap += 16;
        float4 k0 = *(const float4*)Bp;
        float4 k1 = *(const float4*)(Bp + 4);
        Bp += 16;
        As[sk+0][sm] = f2tf32(a0.x); As[sk+1][sm] = f2tf32(a0.y);
        As[sk+2][sm] = f2tf32(a0.z); As[sk+3][sm] = f2tf32(a0.w);
        As[sk+4][sm] = f2tf32(a1.x); As[sk+5][sm] = f2tf32(a1.y);
        As[sk+6][sm] = f2tf32(a1.z); As[sk+7][sm] = f2tf32(a1.w);
        Bs[sk+0][sm] = f2tf32(k0.x); Bs[sk+1][sm] = f2tf32(k0.y);
        Bs[sk+2][sm] = f2tf32(k0.z); Bs[sk+3][sm] = f2tf32(k0.w);
        Bs[sk+4][sm] = f2tf32(k1.x); Bs[sk+5][sm] = f2tf32(k1.y);
        Bs[sk+6][sm] = f2tf32(k1.z); Bs[sk+7][sm] = f2tf32(k1.w);
        __syncthreads();
        #pragma unroll
        for (int ks = 0; ks < 2; ks++) {
            int kr = ks * 8 + (lane & 3);
            int mr = wm + (lane >> 2);
            int nr = wn + (lane >> 2);
            uint32_t af[4][4], bf[4][2];
            #pragma unroll
            for (int mt = 0; mt < 4; mt++) {
                af[mt][0] = As[kr][mr + mt*16];
                af[mt][1] = As[kr][mr + mt*16 + 8];
                af[mt][2] = As[kr+4][mr + mt*16];
                af[mt][3] = As[kr+4][mr + mt*16 + 8];
            }
            #pragma unroll
            for (int nt = 0; nt < 4; nt++) {
                bf[nt][0] = Bs[kr][nr + nt*8];
                bf[nt][1] = Bs[kr+4][nr + nt*8];
            }
            #pragma unroll
            for (int mt = 0; mt < 4; mt++)
                #pragma unroll
                for (int nt = 0; nt < 4; nt++)
                    MMA_TF32(c[mt][nt], af[mt], bf[nt]);
        }
        __syncthreads();
    }
    const float scale = 0.125f;
    int col0 = n0 + wn + 2 * (lane & 3);
    int row0 = m0 + wm + (lane >> 2);
    #pragma unroll
    for (int mt = 0; mt < 4; mt++)
        #pragma unroll
        for (int nt = 0; nt < 4; nt++) {
            float* Cp = g_dots + ((size_t)z * SEQ + row0 + mt*16) * SEQ + col0 + nt*8;
            *(float2*)Cp = make_float2(c[mt][nt][0]*scale, c[mt][nt][1]*scale);
            *(float2*)(Cp + (size_t)8 * SEQ) = make_float2(c[mt][nt][2]*scale, c[mt][nt][3]*scale);
        }
}

// ============================================================ pre-mix -> softmax -> post-mix (per batch)
__global__ __launch_bounds__(256)
void mixsoftmax_kernel(const float* __restrict__ mix_pre, const float* __restrict__ mix_post,
                       int b) {
    extern __shared__ float srow[];          // [NH][SEQ]
    __shared__ float mp[256], mq[256];
    __shared__ float red[NH][8];
    __shared__ float mg[NH], linv[NH];
    int t = threadIdx.x;
    int i = blockIdx.x;
    mp[t] = mix_pre[t];
    mq[t] = mix_post[t];
    size_t base = ((size_t)(b * NH) * SEQ + i) * SEQ;
    for (int h = 0; h < NH; h++) {
        const float4* src = (const float4*)(g_dots + base + (size_t)h * SEQ * SEQ);
        float4* dst = (float4*)(srow + h * SEQ);
        for (int j = t; j < SEQ/4; j += 256) dst[j] = src[j];
    }
    __syncthreads();
    float tmax[NH];
    #pragma unroll
    for (int g = 0; g < NH; g++) tmax[g] = -3.4e38f;
    for (int j = t; j < SEQ; j += 256) {
        float sh[NH];
        #pragma unroll
        for (int h = 0; h < NH; h++) sh[h] = srow[h*SEQ + j];
        #pragma unroll
        for (int g = 0; g < NH; g++) {
            float v = 0.f;
            #pragma unroll
            for (int h = 0; h < NH; h++) v = fmaf(mp[h*NH + g], sh[h], v);
            srow[g*SEQ + j] = v;
            tmax[g] = fmaxf(tmax[g], v);
        }
    }
    int w = t >> 5, l = t & 31;
    #pragma unroll
    for (int g = 0; g < NH; g++) {
        float v = tmax[g];
        #pragma unroll
        for (int o = 16; o > 0; o >>= 1) v = fmaxf(v, __shfl_xor_sync(0xffffffffu, v, o));
        if (l == 0) red[g][w] = v;
    }
    __syncthreads();
    if (t < NH) {
        float v = red[t][0];
        #pragma unroll
        for (int w2 = 1; w2 < 8; w2++) v = fmaxf(v, red[t][w2]);
        mg[t] = v;
    }
    __syncthreads();
    float tsum[NH];
    #pragma unroll
    for (int g = 0; g < NH; g++) tsum[g] = 0.f;
    for (int j = t; j < SEQ; j += 256) {
        #pragma unroll
        for (int g = 0; g < NH; g++) {
            float e = __expf(srow[g*SEQ + j] - mg[g]);
            srow[g*SEQ + j] = e;
            tsum[g] += e;
        }
    }
    __syncthreads();
    #pragma unroll
    for (int g = 0; g < NH; g++) {
        float v = tsum[g];
        #pragma unroll
        for (int o = 16; o > 0; o >>= 1) v += __shfl_xor_sync(0xffffffffu, v, o);
        if (l == 0) red[g][w] = v;
    }
    __syncthreads();
    if (t < NH) {
        float v = 0.f;
        #pragma unroll
        for (int w2 = 0; w2 < 8; w2++) v += red[t][w2];
        linv[t] = 1.f / v;
    }
    __syncthreads();
    for (int j = t; j < SEQ; j += 256) {
        float ph[NH];
        #pragma unroll
        for (int h = 0; h < NH; h++) ph[h] = srow[h*SEQ + j] * linv[h];
        #pragma unroll
        for (int g = 0; g < NH; g++) {
            float v = 0.f;
            #pragma unroll
            for (int h = 0; h < NH; h++) v = fmaf(mq[h*NH + g], ph[h], v);
            g_dots[base + (size_t)g*SEQ*SEQ + j] = v;
        }
    }
}

// ============================================================ O_g = A'_g @ V_g (per batch)
__global__ __launch_bounds__(256)
void av_mma_kernel(int b) {
    __shared__ uint32_t As[16][136];
    __shared__ uint32_t Bs[16][72];
    int t = threadIdx.x, lane = t & 31, w = t >> 5;
    int wm = (w & 3) * 32, wn = (w >> 2) * 32;
    int g = blockIdx.y, z = b * 16 + g;
    const float* Am = g_dots + (size_t)z * SEQ * SEQ;
    const float* Vb = g_qkv + (size_t)b * SEQ * QKVC + 2048 + g * DH;
    int m0 = blockIdx.x * 128;
    int sm = t >> 1, sk = (t & 1) * 8;
    int bk = t >> 4, bn = (t & 15) * 4;
    const float* Ap = Am + (size_t)(m0 + sm) * SEQ + sk;
    const float* Bp = Vb + (size_t)bk * QKVC + bn;
    float c[2][4][4] = {};
    for (int kk = 0; kk < SEQ; kk += 16) {
        float4 a0 = *(const float4*)Ap;
        float4 a1 = *(const float4*)(Ap + 4);
        Ap += 16;
        float4 bv = *(const float4*)Bp;
        Bp += (size_t)16 * QKVC;
        As[sk+0][sm] = f2tf32(a0.x); As[sk+1][sm] = f2tf32(a0.y);
        As[sk+2][sm] = f2tf32(a0.z); As[sk+3][sm] = f2tf32(a0.w);
        As[sk+4][sm] = f2tf32(a1.x); As[sk+5][sm] = f2tf32(a1.y);
        As[sk+6][sm] = f2tf32(a1.z); As[sk+7][sm] = f2tf32(a1.w);
        *(uint4*)&Bs[bk][bn] = make_uint4(f2tf32(bv.x), f2tf32(bv.y), f2tf32(bv.z), f2tf32(bv.w));
        __syncthreads();
        #pragma unroll
        for (int ks = 0; ks < 2; ks++) {
            int kr = ks * 8 + (lane & 3);
            int mr = wm + (lane >> 2);
            int nr = wn + (lane >> 2);
            uint32_t af[2][4], bf[4][2];
            #pragma unroll
            for (int mt = 0; mt < 2; mt++) {
                af[mt][0] = As[kr][mr + mt*16];
                af[mt][1] = As[kr][mr + mt*16 + 8];
                af[mt][2] = As[kr+4][mr + mt*16];
                af[mt][3] = As[kr+4][mr + mt*16 + 8];
            }
            #pragma unroll
            for (int nt = 0; nt < 4; nt++) {
                bf[nt][0] = Bs[kr][nr + nt*8];
                bf[nt][1] = Bs[kr+4][nr + nt*8];
            }
            #pragma unroll
            for (int mt = 0; mt < 2; mt++)
                #pragma unroll
                for (int nt = 0; nt < 4; nt++)
                    MMA_TF32(c[mt][nt], af[mt], bf[nt]);
        }
        __syncthreads();
    }
    int col0 = wn + 2 * (lane & 3);
    int row0 = m0 + wm + (lane >> 2);
    #pragma unroll
    for (int mt = 0; mt < 2; mt++)
        #pragma unroll
        for (int nt = 0; nt < 4; nt++) {
            float* Cp = g_ao + ((size_t)z * SEQ + row0 + mt*16) * DH + col0 + nt*8;
            *(float2*)Cp = make_float2(c[mt][nt][0], c[mt][nt][1]);
            *(float2*)(Cp + (size_t)8 * DH) = make_float2(c[mt][nt][2], c[mt][nt][3]);
        }
}

// ============================================================ out = O @ Wout + bout
__global__ __launch_bounds__(256)
void out_mma_kernel(const float* __restrict__ Wout, const float* __restrict__ bout,
                    float* __restrict__ out) {
    __shared__ uint32_t As[16][136];
    __shared__ uint32_t Bs[16][136];
    int t = threadIdx.x, lane = t & 31, w = t >> 5;
    int wm = (w & 1) * 64, wn = (w >> 1) * 32;
    int m0 = blockIdx.y * 128, n0 = blockIdx.x * 128;
    int sa_m = t >> 1, sa_k = (t & 1) * 8;
    int sb_k = t >> 4, sb_n = (t & 15) * 8;
    int row = m0 + sa_m;
    int bb = row >> 11, ii = row & (SEQ - 1);
    const float* Bptr = Wout + (size_t)sb_k * DIMC + n0 + sb_n;
    float c[4][4][4] = {};
    for (int kk = 0; kk < DIMC; kk += 16) {
        int k = kk + sa_k;
        int gh = k >> 6, d = k & 63;
        const float* Ap = g_ao + ((size_t)(bb * NH + gh) * SEQ + ii) * DH + d;
        float4 a0 = *(const float4*)Ap;
        float4 a1 = *(const float4*)(Ap + 4);
        float4 b0 = *(const float4*)Bptr;
        float4 b1 = *(const float4*)(Bptr + 4);
        Bptr += (size_t)16 * DIMC;
        As[sa_k+0][sa_m] = f2tf32(a0.x); As[sa_k+1][sa_m] = f2tf32(a0.y);
        As[sa_k+2][sa_m] = f2tf32(a0.z); As[sa_k+3][sa_m] = f2tf32(a0.w);
        As[sa_k+4][sa_m] = f2tf32(a1.x); As[sa_k+5][sa_m] = f2tf32(a1.y);
        As[sa_k+6][sa_m] = f2tf32(a1.z); As[sa_k+7][sa_m] = f2tf32(a1.w);
        *(uint4*)&Bs[sb_k][sb_n]   = make_uint4(f2tf32(b0.x), f2tf32(b0.y), f2tf32(b0.z), f2tf32(b0.w));
        *(uint4*)&Bs[sb_k][sb_n+4] = make_uint4(f2tf32(b1.x), f2tf32(b1.y), f2tf32(b1.z), f2tf32(b1.w));
        __syncthreads();
        #pragma unroll
        for (int ks = 0; ks < 2; ks++) {
            int kr = ks * 8 + (lane & 3);
            int mr = wm + (lane >> 2);
            int nr = wn + (lane >> 2);
            uint32_t af[4][4], bf[4][2];
            #pragma unroll
            for (int mt = 0; mt < 4; mt++) {
                af[mt][0] = As[kr][mr + mt*16];
                af[mt][1] = As[kr][mr + mt*16 + 8];
                af[mt][2] = As[kr+4][mr + mt*16];
                af[mt][3] = As[kr+4][mr + mt*16 + 8];
            }
            #pragma unroll
            for (int nt = 0; nt < 4; nt++) {
                bf[nt][0] = Bs[kr][nr + nt*8];
                bf[nt][1] = Bs[kr+4][nr + nt*8];
            }
            #pragma unroll
            for (int mt = 0; mt < 4; mt++)
                #pragma unroll
                for (int nt = 0; nt < 4; nt++)
                    MMA_TF32(c[mt][nt], af[mt], bf[nt]);
        }
        __syncthreads();
    }
    int col0 = n0 + wn + 2 * (lane & 3);
    int row0 = m0 + wm + (lane >> 2);
    #pragma unroll
    for (int nt = 0; nt < 4; nt++) {
        float b0v = bout[col0 + nt*8];
        float b1v = bout[col0 + nt*8 + 1];
        #pragma unroll
        for (int mt = 0; mt < 4; mt++) {
            float* Cp = out + (size_t)(row0 + mt*16) * DIMC + col0 + nt*8;
            *(float2*)Cp = make_float2(c[mt][nt][0] + b0v, c[mt][nt][1] + b1v);
            *(float2*)(Cp + (size_t)8 * DIMC) = make_float2(c[mt][nt][2] + b0v, c[mt][nt][3] + b1v);
        }
    }
}

// ============================================================ launch: batch-pipelined, mix on s1
extern "C" void kernel_launch(void* const* d_in, const int* in_sizes, int n_in,
                              void* d_out, int out_size) {
    const float* x       = (const float*)d_in[0];
    const float* ln_g    = (const float*)d_in[1];
    const float* ln_b    = (const float*)d_in[2];
    const float* Wq      = (const float*)d_in[3];
    const float* Wkv     = (const float*)d_in[4];
    const float* mixpre  = (const float*)d_in[5];
    const float* mixpost = (const float*)d_in[6];
    const float* Wout    = (const float*)d_in[7];
    const float* bout    = (const float*)d_in[8];
    float* out = (float*)d_out;

    static bool init0 = false;
    static cudaStream_t s1;
    static cudaEvent_t evRoot, evQ0, evQ1, evM0, evM1;
    if (!init0) {
        cudaStreamCreateWithFlags(&s1, cudaStreamNonBlocking);
        cudaEventCreateWithFlags(&evRoot, cudaEventDisableTiming);
        cudaEventCreateWithFlags(&evQ0, cudaEventDisableTiming);
        cudaEventCreateWithFlags(&evQ1, cudaEventDisableTiming);
        cudaEventCreateWithFlags(&evM0, cudaEventDisableTiming);
        cudaEventCreateWithFlags(&evM1, cudaEventDisableTiming);
        cudaFuncSetAttribute(mixsoftmax_kernel,
                             cudaFuncAttributeMaxDynamicSharedMemorySize, NH * SEQ * 4);
        init0 = true;
    }

    // fork s1 from the capture stream
    cudaEventRecord(evRoot, 0);
    cudaStreamWaitEvent(s1, evRoot, 0);

    ln_kernel<<<NROWS, 256>>>(x, ln_g, ln_b);
    proj_mma_kernel<<<dim3(24, 32), 256>>>(Wq, Wkv);

    qk_mma_kernel<<<dim3(16, 16, 16), 256>>>(0);
    cudaEventRecord(evQ0, 0);
    qk_mma_kernel<<<dim3(16, 16, 16), 256>>>(1);
    cudaEventRecord(evQ1, 0);

    // mixsoftmax on s1: mix(b0) overlaps qk(b1); mix(b1) overlaps av(b0)
    cudaStreamWaitEvent(s1, evQ0, 0);
    mixsoftmax_kernel<<<SEQ, 256, NH * SEQ * 4, s1>>>(mixpre, mixpost, 0);
    cudaEventRecord(evM0, s1);
    cudaStreamWaitEvent(s1, evQ1, 0);
    mixsoftmax_kernel<<<SEQ, 256, NH * SEQ * 4, s1>>>(mixpre, mixpost, 1);
    cudaEventRecord(evM1, s1);

    cudaStreamWaitEvent(0, evM0, 0);
    av_mma_kernel<<<dim3(16, 16), 256>>>(0);
    cudaStreamWaitEvent(0, evM1, 0);
    av_mma_kernel<<<dim3(16, 16), 256>>>(1);

    out_mma_kernel<<<dim3(8, 32), 256>>>(Wout, bout, out);
}